// round 16
// baseline (speedup 1.0000x reference)
#include <cuda_runtime.h>
#include <math.h>

#ifndef M_PI
#define M_PI 3.14159265358979323846
#endif

#define Bb 8
#define B2 16
#define Hh 160
#define Ww 180
#define NPIX (Hh*Ww)          /* 28800 */
#define NIMG (Bb*NPIX)
#define NIMG2 (B2*NPIX)
#define NFEAT2 (B2*32*NPIX)
#define DELTA 0.01f

typedef unsigned long long ull;

/* ------------------------- scratch (device globals) ------------------------- */
__device__ float2 g_X[NIMG2], g_C[NIMG2];
__device__ float2 g_ta[NIMG2], g_tb[NIMG2], g_gf[NIMG2];
__device__ float2 g_act0[NFEAT2], g_act1[NFEAT2], g_act2[NFEAT2];
__device__ float2 g_fb0[NFEAT2], g_fb1[NFEAT2];
__device__ ulonglong2 g_twW[Ww], g_twWi[Ww];
__device__ ulonglong2 g_MH2[Hh*Hh], g_MH2i[Hh*Hh];

/* ------------------------------- device math ------------------------------- */
__device__ __forceinline__ float actf(float x){
    if (fabsf(x) > DELTA) return x > 0.f ? x : 0.f;
    return x*x*(1.f/(4.f*DELTA)) + 0.5f*x + DELTA*0.25f;
}
__device__ __forceinline__ float actd(float x){
    if (fabsf(x) > DELTA) return x > 0.f ? 1.f : 0.f;
    return x*(1.f/(2.f*DELTA)) + 0.5f;
}
__device__ __forceinline__ ull pk2(float lo, float hi){
    ull r; asm("mov.b64 %0, {%1, %2};" : "=l"(r) : "f"(lo), "f"(hi)); return r;
}
__device__ __forceinline__ void upk2(ull v, float& lo, float& hi){
    asm("mov.b64 {%0, %1}, %2;" : "=f"(lo), "=f"(hi) : "l"(v));
}
__device__ __forceinline__ void fma2(ull& acc, ull a, ull b){
    asm("fma.rn.f32x2 %0, %1, %2, %0;" : "+l"(acc) : "l"(a), "l"(b));
}

/* ------------------------------ setup kernels ------------------------------ */
__global__ void k_init_dft(){
    int i = blockIdx.x*blockDim.x + threadIdx.x;
    if (i < Ww){
        double ang = -2.0*M_PI*(double)i/(double)Ww;
        double s, c; sincos(ang, &s, &c);
        float cf = (float)c, sf = (float)s;
        g_twW[i]  = make_ulonglong2(pk2(cf, sf), pk2(sf, cf));
        float ci = (float)(c/(double)Ww), si = (float)(-s/(double)Ww);
        g_twWi[i] = make_ulonglong2(pk2(ci, si), pk2(si, ci));
    }
    if (i < Hh*Hh){
        int u = i / Hh, h = i % Hh;
        int t = (u*h) % Hh;
        double ang = -2.0*M_PI*(double)t/(double)Hh;
        double s, c; sincos(ang, &s, &c);
        float cf = (float)c, sf = (float)s;
        g_MH2[i]  = make_ulonglong2(pk2(cf, sf), pk2(sf, cf));
        float ci = (float)(c/(double)Hh), si = (float)(-s/(double)Hh);
        g_MH2i[i] = make_ulonglong2(pk2(ci, si), pk2(si, ci));
    }
}

__global__ void k_pack2(const float* __restrict__ s1, const float* __restrict__ s2,
                        float2* __restrict__ d){
    int i = blockIdx.x*blockDim.x + threadIdx.x;
    if (i >= NIMG2) return;
    int b = i / NPIX, p = i % NPIX;
    const float* s = (b < Bb) ? s1 : s2;
    int bb = b & 7;
    d[i] = make_float2(s[(size_t)(bb*2+0)*NPIX + p], s[(size_t)(bb*2+1)*NPIX + p]);
}

__global__ void k_maskk2(const float* __restrict__ k1, const float* __restrict__ k2,
                         const float* __restrict__ mask, float2* __restrict__ d){
    int i = blockIdx.x*blockDim.x + threadIdx.x;
    if (i >= NIMG2) return;
    int b = i / NPIX, p = i % NPIX;
    const float* k = (b < Bb) ? k1 : k2;
    int bb = b & 7;
    float m = mask[p];
    d[i] = make_float2(m*k[(size_t)(bb*2+0)*NPIX + p], m*k[(size_t)(bb*2+1)*NPIX + p]);
}

/* ------------------------------- DFT kernels ------------------------------- */
__global__ void __launch_bounds__(360)
k_dftrow(const float2* __restrict__ in, float2* __restrict__ out,
         const ulonglong2* __restrict__ tw){
    __shared__ ulonglong2 sx[8][Ww];
    __shared__ ull sred[8][Ww];
    __shared__ ulonglong2 stw[192];
    int r0 = blockIdx.x*8;
    for (int t = threadIdx.x; t < 8*Ww; t += 360){
        int r = t / Ww, w = t % Ww;
        float2 x = in[(size_t)(r0+r)*Ww + w];
        sx[r][w] = make_ulonglong2(pk2(x.x, x.x), pk2(-x.y, x.y));
    }
    for (int t = threadIdx.x; t < Ww; t += 360)
        stw[t + (t >> 4)] = tw[t];
    __syncthreads();
    int half = threadIdx.x / Ww;
    int u = threadIdx.x % Ww;
    ull acc[8];
    #pragma unroll
    for (int r = 0; r < 8; r++) acc[r] = 0ULL;
    int wlo = half*90;
    int idx = (wlo*u) % Ww;
    #pragma unroll 2
    for (int w = wlo; w < wlo+90; w++){
        ulonglong2 m = stw[idx + (idx >> 4)];
        idx += u; if (idx >= Ww) idx -= Ww;
        #pragma unroll
        for (int r = 0; r < 8; r++){
            ulonglong2 xv = sx[r][w];
            fma2(acc[r], xv.x, m.x);
            fma2(acc[r], xv.y, m.y);
        }
    }
    if (half == 1){
        #pragma unroll
        for (int r = 0; r < 8; r++) sred[r][u] = acc[r];
    }
    __syncthreads();
    if (half == 0){
        #pragma unroll
        for (int r = 0; r < 8; r++){
            float a, b2, c, d; upk2(acc[r], a, b2); upk2(sred[r][u], c, d);
            out[(size_t)(r0+r)*Ww + u] = make_float2(a+c, b2+d);
        }
    }
}

template<int FUSE_MASK>
__global__ void __launch_bounds__(360)
k_dftcol(const float2* __restrict__ in, float2* __restrict__ out,
         const ulonglong2* __restrict__ M2, const float* __restrict__ mask){
    __shared__ ulonglong2 sm[8][Hh];
    __shared__ ull sred[8][Ww];
    int u0 = blockIdx.x*8, b = blockIdx.y;
    for (int t = threadIdx.x; t < 8*Hh; t += 360){
        int j = t / Hh, h = t % Hh;
        sm[j][h] = M2[(u0+j)*Hh + h];
    }
    __syncthreads();
    int half = threadIdx.x / Ww;
    int w = threadIdx.x % Ww;
    const float2* ip = in + (size_t)b*NPIX + w;
    ull acc[8];
    #pragma unroll
    for (int j = 0; j < 8; j++) acc[j] = 0ULL;
    int hlo = half*80;
    #pragma unroll 2
    for (int h = hlo; h < hlo+80; h++){
        float2 x = ip[h*Ww];
        ull xr = pk2(x.x, x.x), xn = pk2(-x.y, x.y);
        #pragma unroll
        for (int j = 0; j < 8; j++){
            fma2(acc[j], xr, sm[j][h].x);
            fma2(acc[j], xn, sm[j][h].y);
        }
    }
    if (half == 1){
        #pragma unroll
        for (int j = 0; j < 8; j++) sred[j][w] = acc[j];
    }
    __syncthreads();
    if (half == 0){
        #pragma unroll
        for (int j = 0; j < 8; j++){
            float a, b2, c, d; upk2(acc[j], a, b2); upk2(sred[j][w], c, d);
            float sr = a+c, si = b2+d;
            if (FUSE_MASK){
                float mv = mask[(u0+j)*Ww + w]; mv *= mv;
                sr *= mv; si *= mv;
            }
            out[(size_t)b*NPIX + (u0+j)*Ww + w] = make_float2(sr, si);
        }
    }
}

/* --- Gauss packed conv: 4 outs x 4 vert px, smem input tile, 16 warps/SM --- */
/* EPI: 0=none, 1=smoothed-ReLU, 2=complex-mul by act-derivative */
#define TR 18              /* tile rows: 16 + 2 halo */
#define TCL 34             /* tile cols: 32 + 2 halo */
#define TCS 36             /* padded col stride */
template<int CS, int TRANS, int EPI>
__global__ void __launch_bounds__(128, 4)
k_convS(const float2* __restrict__ in,
        const float* __restrict__ wrA, const float* __restrict__ wiA,
        const float* __restrict__ wrB, const float* __restrict__ wiB,
        float2* __restrict__ out, const float2* __restrict__ act)
{
    extern __shared__ ull smem_raw[];
    ull*    swp   = smem_raw;                      /* [CS*9][4] packed (wr,wi) */
    float*  sws   = (float*)(smem_raw + CS*9*4);   /* [CS*9][4] ws=wr+wi       */
    float2* stile = (float2*)(sws + CS*9*4);       /* [TR][TCS] input tile     */

    const int z  = blockIdx.x & 7;
    const int wt = blockIdx.x >> 3;
    const int b  = blockIdx.z;
    const float* wr = (b < Bb) ? wrA : wrB;
    const float* wi = (b < Bb) ? wiA : wiB;
    const int tid = threadIdx.x;

    for (int t = tid; t < CS*9*4; t += 128){
        int o4 = t & 3; int tap = (t >> 2) % 9; int c = t/36;
        int o = z*4 + o4;
        int ky = tap/3, kx = tap%3;
        int widx = TRANS ? ((c*32 + o)*9 + (2-ky)*3 + (2-kx))
                         : ((o*CS + c)*9 + tap);
        float a = wr[widx], q = wi[widx];
        swp[t] = pk2(a, q);
        sws[t] = a + q;
    }

    const int tx = tid & 31, ty = tid >> 5;
    const int wb = wt*32, hb = blockIdx.y*16;
    const int w  = wb + tx;
    const int h0 = hb + ty*4;
    const bool valid = (w < Ww);

    ull m12[4][4];
    ull m3 [4][2];
    #pragma unroll
    for (int py = 0; py < 4; py++){
        #pragma unroll
        for (int o = 0; o < 4; o++) m12[py][o] = 0ULL;
        m3[py][0] = 0ULL; m3[py][1] = 0ULL;
    }

    const float2* ip = in + (size_t)b*CS*NPIX;
    for (int c = 0; c < CS; c++, ip += NPIX){
        __syncthreads();
        /* cooperative tile load: rows hb-1..hb+16, cols wb-1..wb+32 */
        for (int t = tid; t < TR*TCL; t += 128){
            int r = t / TCL, cl = t % TCL;
            int gy = hb + r - 1, gx = wb + cl - 1;
            float2 v = make_float2(0.f, 0.f);
            if (gy >= 0 && gy < Hh && gx >= 0 && gx < Ww)
                v = ip[gy*Ww + gx];
            stile[r*TCS + cl] = v;
        }
        __syncthreads();

        ull xc[6][3];
        #pragma unroll
        for (int r = 0; r < 6; r++){
            const float2* sp = stile + (ty*4 + r)*TCS + tx;
            float2 v0 = sp[0], v1 = sp[1], v2 = sp[2];
            xc[r][0] = pk2(v0.x, v0.y);
            xc[r][1] = pk2(v1.x, v1.y);
            xc[r][2] = pk2(v2.x, v2.y);
        }
        #pragma unroll
        for (int kx = 0; kx < 3; kx++){
            ull xs6[6];
            #pragma unroll
            for (int r = 0; r < 6; r++){
                float lo, hi; upk2(xc[r][kx], lo, hi);
                float s = lo + hi;
                xs6[r] = pk2(s, s);
            }
            #pragma unroll
            for (int ky = 0; ky < 3; ky++){
                const int tap = ky*3 + kx;
                const ulonglong2* wp  = (const ulonglong2*)(swp + (c*9 + tap)*4);
                const ulonglong2* wsp = ((const ulonglong2*)sws) + (c*9 + tap);
                ulonglong2 wv0 = wp[0], wv1 = wp[1];
                ulonglong2 sv  = wsp[0];
                #pragma unroll
                for (int py = 0; py < 4; py++){
                    ull xe = xc[ky+py][kx];
                    ull se = xs6[ky+py];
                    fma2(m12[py][0], xe, wv0.x);
                    fma2(m12[py][1], xe, wv0.y);
                    fma2(m12[py][2], xe, wv1.x);
                    fma2(m12[py][3], xe, wv1.y);
                    fma2(m3[py][0], se, sv.x);
                    fma2(m3[py][1], se, sv.y);
                }
            }
        }
    }

    if (!valid) return;
    #pragma unroll
    for (int o = 0; o < 4; o++){
        const size_t ch = (size_t)b*32 + z*4 + o;
        float2* op = out + ch*NPIX + (size_t)h0*Ww + w;
        const float2* ap = act + ch*NPIX + (size_t)h0*Ww + w;
        #pragma unroll
        for (int py = 0; py < 4; py++){
            float m1, m2; upk2(m12[py][o], m1, m2);
            float g3a, g3b; upk2(m3[py][o>>1], g3a, g3b);
            float m3v = (o & 1) ? g3b : g3a;
            float re = m1 - m2;
            float im = m3v - m1 - m2;
            if (EPI == 1){ re = actf(re); im = actf(im); }
            if (EPI == 2){
                float2 a = ap[(size_t)py*Ww];
                float dr = actd(a.x), di = actd(a.y);
                float nre = re*dr - im*di;
                im = re*di + im*dr;
                re = nre;
            }
            op[(size_t)py*Ww] = make_float2(re, im);
        }
    }
}

/* ------------- fused 32->1 transposed conv + gradient update ---------------- */
__global__ void __launch_bounds__(256)
k_t1_update(const float2* __restrict__ in,
            const float* __restrict__ w1rA, const float* __restrict__ w1iA,
            const float* __restrict__ w1rB, const float* __restrict__ w1iB,
            const float2* __restrict__ gf, const float2* __restrict__ cc,
            float2* __restrict__ X,
            const float* __restrict__ al1, const float* __restrict__ al2,
            const float* __restrict__ be1, const float* __restrict__ be2, int ph)
{
    __shared__ ulonglong2 sxt[4][10][34];
    __shared__ ulonglong2 swt[32][9];
    const int tx = threadIdx.x & 31, ty = threadIdx.x >> 5;
    const int tid = threadIdx.x;
    const int wx0 = blockIdx.x*32, hy0 = blockIdx.y*8;
    const int b = blockIdx.z;
    const float* wr = (b < Bb) ? w1rA : w1rB;
    const float* wi = (b < Bb) ? w1iA : w1iB;

    for (int t = tid; t < 288; t += 256){
        int c = t / 9, tap = t % 9;
        int ky = tap/3, kx = tap%3;
        int ft = (2-ky)*3 + (2-kx);
        float a = wr[c*9 + ft], bq = wi[c*9 + ft];
        swt[c][tap] = make_ulonglong2(pk2(a, bq), pk2(bq, a));
    }

    const float2* ib = in + (size_t)b*32*NPIX;
    ull acc = 0ULL;
    for (int cs = 0; cs < 8; cs++){
        __syncthreads();
        for (int t = tid; t < 4*340; t += 256){
            int ch = t / 340, e = t % 340;
            int yy = e / 34, xx = e % 34;
            int gy = hy0 + yy - 1, gx = wx0 + xx - 1;
            float2 v = make_float2(0.f, 0.f);
            if (gy >= 0 && gy < Hh && gx >= 0 && gx < Ww)
                v = ib[(size_t)(cs*4+ch)*NPIX + gy*Ww + gx];
            sxt[ch][yy][xx] = make_ulonglong2(pk2(v.x, v.x), pk2(-v.y, v.y));
        }
        __syncthreads();
        #pragma unroll
        for (int ch = 0; ch < 4; ch++){
            int c = cs*4 + ch;
            #pragma unroll
            for (int tap = 0; tap < 9; tap++){
                int ky = tap/3, kx = tap%3;
                ulonglong2 wv = swt[c][tap];
                ulonglong2 xv = sxt[ch][ty+ky][tx+kx];
                fma2(acc, xv.x, wv.x);
                fma2(acc, xv.y, wv.y);
            }
        }
    }
    int h = hy0 + ty, w = wx0 + tx;
    if (w < Ww){
        float gr, gi; upk2(acc, gr, gi);
        size_t i = (size_t)b*NPIX + h*Ww + w;
        float a  = (b < Bb) ? al1[ph] : al2[ph];
        float be = (b < Bb) ? be1[ph] : be2[ph];
        float2 xv = X[i], f = gf[i], c = cc[i];
        xv.x -= a*(f.x - c.x) + be*gr;
        xv.y -= a*(f.y - c.y) + be*gi;
        X[i] = xv;
    }
}

/* ------------------------- threshold / normalize --------------------------- */
__global__ void k_thresh(const float2* __restrict__ in, float2* __restrict__ out,
                         const float* __restrict__ thr1, const float* __restrict__ thr2){
    int p = blockIdx.x*blockDim.x + threadIdx.x;
    int b = blockIdx.y;
    if (p >= NPIX) return;
    float thr = (b < Bb) ? thr1[0] : thr2[0];
    const float2* ip = in + (size_t)b*32*NPIX + p;
    float nrm = 0.f;
    #pragma unroll 8
    for (int c = 0; c < 32; c++){
        float2 v = ip[(size_t)c*NPIX];
        nrm = fmaf(v.x, v.x, nrm);
        nrm = fmaf(v.y, v.y, nrm);
    }
    nrm = sqrtf(nrm);
    float denom = (nrm > thr) ? fmaxf(nrm, 1e-12f) : thr;
    float inv = 1.f/denom;
    float2* op = out + (size_t)b*32*NPIX + p;
    #pragma unroll 8
    for (int c = 0; c < 32; c++){
        float2 v = ip[(size_t)c*NPIX];
        op[(size_t)c*NPIX] = make_float2(v.x*inv, v.y*inv);
    }
}

__global__ void k_out(const float2* __restrict__ X, float* __restrict__ o){
    int i = blockIdx.x*blockDim.x + threadIdx.x;
    if (i >= NIMG) return;
    int b = i / NPIX, p = i % NPIX;
    size_t base = (size_t)b*4*NPIX + p;
    float2 v1 = X[(size_t)b*NPIX + p];
    float2 v2 = X[(size_t)(b+Bb)*NPIX + p];
    o[base + 0*NPIX] = v1.x;
    o[base + 1*NPIX] = v1.y;
    o[base + 2*NPIX] = v2.x;
    o[base + 3*NPIX] = v2.y;
}

/* --------------------------------- launch ---------------------------------- */
static inline void* symaddr(const void* sym){
    void* p = nullptr;
    cudaGetSymbolAddress(&p, sym);
    return p;
}

extern "C" void kernel_launch(void* const* d_in, const int* in_sizes, int n_in,
                              void* d_out, int out_size){
    const float* x1in  = (const float*)d_in[0];
    const float* x2in  = (const float*)d_in[1];
    const float* k1in  = (const float*)d_in[2];
    const float* k2in  = (const float*)d_in[3];
    const float* mask  = (const float*)d_in[4];
    const float* wA[8], *wB[8];
    for (int j = 0; j < 8; j++){ wA[j] = (const float*)d_in[5+j]; wB[j] = (const float*)d_in[13+j]; }
    const float* thr1  = (const float*)d_in[21];
    const float* thr2  = (const float*)d_in[22];
    const float* al1   = (const float*)d_in[23];
    const float* al2   = (const float*)d_in[24];
    const float* be1   = (const float*)d_in[25];
    const float* be2   = (const float*)d_in[26];

    float2* X   = (float2*)symaddr(g_X);
    float2* C   = (float2*)symaddr(g_C);
    float2* TA  = (float2*)symaddr(g_ta);
    float2* TB  = (float2*)symaddr(g_tb);
    float2* GF  = (float2*)symaddr(g_gf);
    float2* A0  = (float2*)symaddr(g_act0);
    float2* A1  = (float2*)symaddr(g_act1);
    float2* A2  = (float2*)symaddr(g_act2);
    float2* F0  = (float2*)symaddr(g_fb0);
    float2* F1  = (float2*)symaddr(g_fb1);
    ulonglong2* TW   = (ulonglong2*)symaddr(g_twW);
    ulonglong2* TWi  = (ulonglong2*)symaddr(g_twWi);
    ulonglong2* MH2  = (ulonglong2*)symaddr(g_MH2);
    ulonglong2* MH2i = (ulonglong2*)symaddr(g_MH2i);

    const int TPB = 256;
    const int gIMG1 = (NIMG  + TPB - 1)/TPB;
    const int gIMG2 = (NIMG2 + TPB - 1)/TPB;
    const int gPIX  = (NPIX  + TPB - 1)/TPB;
    dim3 gridConv(6*8, 10, B2);        /* bx = wt*8 + z (z adjacent), by = h-tile */
    dim3 gridThr (gPIX, B2);
    dim3 gridRow ((B2*Hh)/8);
    dim3 gridCol (Hh/8, B2);
    dim3 gridT1  ((Ww+31)/32, Hh/8, B2);
    const int TILE_B = TR*TCS*8;                         /* 5184 B */
    const int SMEM_H = 32*9*4*8 + 32*9*4*4 + TILE_B;     /* 19008 B */
    const int SMEM_1 = 1*9*4*8 + 1*9*4*4 + TILE_B;

    k_init_dft<<<(Hh*Hh + TPB - 1)/TPB, TPB>>>();
    k_pack2<<<gIMG2, TPB>>>(x1in, x2in, X);

    for (int ph = 0; ph < 3; ph++){
        /* grad_r chain first (keeps the heavy conv at ncu's launch #6) */
        k_convS<1, 0, 1><<<gridConv, 128, SMEM_1>>>(X,  wA[0], wA[1], wB[0], wB[1], A0, nullptr);
        k_convS<32,0, 1><<<gridConv, 128, SMEM_H>>>(A0, wA[2], wA[3], wB[2], wB[3], A1, nullptr);
        k_convS<32,0, 1><<<gridConv, 128, SMEM_H>>>(A1, wA[4], wA[5], wB[4], wB[5], A2, nullptr);
        k_convS<32,0, 0><<<gridConv, 128, SMEM_H>>>(A2, wA[6], wA[7], wB[6], wB[7], F0, nullptr);
        k_thresh<<<gridThr, TPB>>>(F0, F1, thr1, thr2);
        k_convS<32,1, 2><<<gridConv, 128, SMEM_H>>>(F1, wA[6], wA[7], wB[6], wB[7], F0, A2);
        k_convS<32,1, 2><<<gridConv, 128, SMEM_H>>>(F0, wA[4], wA[5], wB[4], wB[5], F1, A1);
        k_convS<32,1, 2><<<gridConv, 128, SMEM_H>>>(F1, wA[2], wA[3], wB[2], wB[3], F0, A0);

        if (ph == 0){
            k_maskk2<<<gIMG2, TPB>>>(k1in, k2in, mask, TA);
            k_dftrow<<<gridRow, 360>>>(TA, TB, TWi);
            k_dftcol<0><<<gridCol, 360>>>(TB, C, MH2i, nullptr);
        }

        /* grad_f (minus constant): GF = IFFT2(mask^2 * FFT2(X)) */
        k_dftrow<<<gridRow, 360>>>(X,  TA, TW);
        k_dftcol<1><<<gridCol, 360>>>(TA, TB, MH2, mask);
        k_dftrow<<<gridRow, 360>>>(TB, TA, TWi);
        k_dftcol<0><<<gridCol, 360>>>(TA, GF, MH2i, nullptr);

        /* 32->1 transposed conv fused with the x update */
        k_t1_update<<<gridT1, 256>>>(F0, wA[0], wA[1], wB[0], wB[1],
                                     GF, C, X, al1, al2, be1, be2, ph);
    }
    k_out<<<gIMG1, TPB>>>(X, (float*)d_out);
}

// round 17
// speedup vs baseline: 2.7456x; 2.7456x over previous
#include <cuda_runtime.h>
#include <math.h>

#ifndef M_PI
#define M_PI 3.14159265358979323846
#endif

#define Bb 8
#define B2 16
#define Hh 160
#define Ww 180
#define NPIX (Hh*Ww)          /* 28800 */
#define NIMG (Bb*NPIX)
#define NIMG2 (B2*NPIX)
#define NFEAT2 (B2*32*NPIX)
#define DELTA 0.01f

typedef unsigned long long ull;

/* ------------------------- scratch (device globals) ------------------------- */
__device__ float2 g_X[NIMG2], g_C[NIMG2];
__device__ float2 g_ta[NIMG2], g_tb[NIMG2], g_gf[NIMG2];
__device__ float2 g_act0[NFEAT2], g_act1[NFEAT2], g_act2[NFEAT2];
__device__ float2 g_fb0[NFEAT2], g_fb1[NFEAT2];
__device__ ulonglong2 g_twW[Ww], g_twWi[Ww];
__device__ ulonglong2 g_MH2[Hh*Hh], g_MH2i[Hh*Hh];

/* ------------------------------- device math ------------------------------- */
__device__ __forceinline__ float actf(float x){
    if (fabsf(x) > DELTA) return x > 0.f ? x : 0.f;
    return x*x*(1.f/(4.f*DELTA)) + 0.5f*x + DELTA*0.25f;
}
__device__ __forceinline__ float actd(float x){
    if (fabsf(x) > DELTA) return x > 0.f ? 1.f : 0.f;
    return x*(1.f/(2.f*DELTA)) + 0.5f;
}
__device__ __forceinline__ ull pk2(float lo, float hi){
    ull r; asm("mov.b64 %0, {%1, %2};" : "=l"(r) : "f"(lo), "f"(hi)); return r;
}
__device__ __forceinline__ void upk2(ull v, float& lo, float& hi){
    asm("mov.b64 {%0, %1}, %2;" : "=f"(lo), "=f"(hi) : "l"(v));
}
__device__ __forceinline__ void fma2(ull& acc, ull a, ull b){
    asm("fma.rn.f32x2 %0, %1, %2, %0;" : "+l"(acc) : "l"(a), "l"(b));
}

/* ------------------------------ setup kernels ------------------------------ */
__global__ void k_init_dft(){
    int i = blockIdx.x*blockDim.x + threadIdx.x;
    if (i < Ww){
        double ang = -2.0*M_PI*(double)i/(double)Ww;
        double s, c; sincos(ang, &s, &c);
        float cf = (float)c, sf = (float)s;
        g_twW[i]  = make_ulonglong2(pk2(cf, sf), pk2(sf, cf));
        float ci = (float)(c/(double)Ww), si = (float)(-s/(double)Ww);
        g_twWi[i] = make_ulonglong2(pk2(ci, si), pk2(si, ci));
    }
    if (i < Hh*Hh){
        int u = i / Hh, h = i % Hh;
        int t = (u*h) % Hh;
        double ang = -2.0*M_PI*(double)t/(double)Hh;
        double s, c; sincos(ang, &s, &c);
        float cf = (float)c, sf = (float)s;
        g_MH2[i]  = make_ulonglong2(pk2(cf, sf), pk2(sf, cf));
        float ci = (float)(c/(double)Hh), si = (float)(-s/(double)Hh);
        g_MH2i[i] = make_ulonglong2(pk2(ci, si), pk2(si, ci));
    }
}

__global__ void k_pack2(const float* __restrict__ s1, const float* __restrict__ s2,
                        float2* __restrict__ d){
    int i = blockIdx.x*blockDim.x + threadIdx.x;
    if (i >= NIMG2) return;
    int b = i / NPIX, p = i % NPIX;
    const float* s = (b < Bb) ? s1 : s2;
    int bb = b & 7;
    d[i] = make_float2(s[(size_t)(bb*2+0)*NPIX + p], s[(size_t)(bb*2+1)*NPIX + p]);
}

__global__ void k_maskk2(const float* __restrict__ k1, const float* __restrict__ k2,
                         const float* __restrict__ mask, float2* __restrict__ d){
    int i = blockIdx.x*blockDim.x + threadIdx.x;
    if (i >= NIMG2) return;
    int b = i / NPIX, p = i % NPIX;
    const float* k = (b < Bb) ? k1 : k2;
    int bb = b & 7;
    float m = mask[p];
    d[i] = make_float2(m*k[(size_t)(bb*2+0)*NPIX + p], m*k[(size_t)(bb*2+1)*NPIX + p]);
}

/* ------------------------------- DFT kernels ------------------------------- */
__global__ void __launch_bounds__(360)
k_dftrow(const float2* __restrict__ in, float2* __restrict__ out,
         const ulonglong2* __restrict__ tw){
    __shared__ ulonglong2 sx[8][Ww];
    __shared__ ull sred[8][Ww];
    __shared__ ulonglong2 stw[192];
    int r0 = blockIdx.x*8;
    for (int t = threadIdx.x; t < 8*Ww; t += 360){
        int r = t / Ww, w = t % Ww;
        float2 x = in[(size_t)(r0+r)*Ww + w];
        sx[r][w] = make_ulonglong2(pk2(x.x, x.x), pk2(-x.y, x.y));
    }
    for (int t = threadIdx.x; t < Ww; t += 360)
        stw[t + (t >> 4)] = tw[t];
    __syncthreads();
    int half = threadIdx.x / Ww;
    int u = threadIdx.x % Ww;
    ull acc[8];
    #pragma unroll
    for (int r = 0; r < 8; r++) acc[r] = 0ULL;
    int wlo = half*90;
    int idx = (wlo*u) % Ww;
    #pragma unroll 2
    for (int w = wlo; w < wlo+90; w++){
        ulonglong2 m = stw[idx + (idx >> 4)];
        idx += u; if (idx >= Ww) idx -= Ww;
        #pragma unroll
        for (int r = 0; r < 8; r++){
            ulonglong2 xv = sx[r][w];
            fma2(acc[r], xv.x, m.x);
            fma2(acc[r], xv.y, m.y);
        }
    }
    if (half == 1){
        #pragma unroll
        for (int r = 0; r < 8; r++) sred[r][u] = acc[r];
    }
    __syncthreads();
    if (half == 0){
        #pragma unroll
        for (int r = 0; r < 8; r++){
            float a, b2, c, d; upk2(acc[r], a, b2); upk2(sred[r][u], c, d);
            out[(size_t)(r0+r)*Ww + u] = make_float2(a+c, b2+d);
        }
    }
}

template<int FUSE_MASK>
__global__ void __launch_bounds__(360)
k_dftcol(const float2* __restrict__ in, float2* __restrict__ out,
         const ulonglong2* __restrict__ M2, const float* __restrict__ mask){
    __shared__ ulonglong2 sm[8][Hh];
    __shared__ ull sred[8][Ww];
    int u0 = blockIdx.x*8, b = blockIdx.y;
    for (int t = threadIdx.x; t < 8*Hh; t += 360){
        int j = t / Hh, h = t % Hh;
        sm[j][h] = M2[(u0+j)*Hh + h];
    }
    __syncthreads();
    int half = threadIdx.x / Ww;
    int w = threadIdx.x % Ww;
    const float2* ip = in + (size_t)b*NPIX + w;
    ull acc[8];
    #pragma unroll
    for (int j = 0; j < 8; j++) acc[j] = 0ULL;
    int hlo = half*80;
    #pragma unroll 2
    for (int h = hlo; h < hlo+80; h++){
        float2 x = ip[h*Ww];
        ull xr = pk2(x.x, x.x), xn = pk2(-x.y, x.y);
        #pragma unroll
        for (int j = 0; j < 8; j++){
            fma2(acc[j], xr, sm[j][h].x);
            fma2(acc[j], xn, sm[j][h].y);
        }
    }
    if (half == 1){
        #pragma unroll
        for (int j = 0; j < 8; j++) sred[j][w] = acc[j];
    }
    __syncthreads();
    if (half == 0){
        #pragma unroll
        for (int j = 0; j < 8; j++){
            float a, b2, c, d; upk2(acc[j], a, b2); upk2(sred[j][w], c, d);
            float sr = a+c, si = b2+d;
            if (FUSE_MASK){
                float mv = mask[(u0+j)*Ww + w]; mv *= mv;
                sr *= mv; si *= mv;
            }
            out[(size_t)b*NPIX + (u0+j)*Ww + w] = make_float2(sr, si);
        }
    }
}

/* --- Gauss packed conv: 4 outputs x 4 pixels, 8:1 fma:LDS, 16 warps/SM ----- */
/* EPI: 0=none, 1=smoothed-ReLU, 2=complex-mul by act-derivative */
template<int CS, int TRANS, int EPI>
__global__ void __launch_bounds__(128, 4)
k_conv4(const float2* __restrict__ in,
        const float* __restrict__ wrA, const float* __restrict__ wiA,
        const float* __restrict__ wrB, const float* __restrict__ wiB,
        float2* __restrict__ out, const float2* __restrict__ act)
{
    extern __shared__ ull smem_raw[];
    ull*   swp  = smem_raw;                      /* [CS*9][4] packed (wr,wi) */
    float* sws  = (float*)(smem_raw + CS*9*4);   /* [CS*9][4] ws=wr+wi       */

    const int z    = blockIdx.x & 7;             /* output quartet, z adjacent */
    const int colb = blockIdx.x >> 3;
    const int b = blockIdx.y;
    const float* wr = (b < Bb) ? wrA : wrB;
    const float* wi = (b < Bb) ? wiA : wiB;

    for (int t = threadIdx.x; t < CS*9*4; t += 128){
        int o4 = t & 3; int tap = (t >> 2) % 9; int c = t/36;
        int o = z*4 + o4;
        int ky = tap/3, kx = tap%3;
        int widx = TRANS ? ((c*32 + o)*9 + (2-ky)*3 + (2-kx))
                         : ((o*CS + c)*9 + tap);
        float a = wr[widx], q = wi[widx];
        swp[t] = pk2(a, q);
        sws[t] = a + q;
    }
    __syncthreads();

    const int p0 = colb*512 + 4*threadIdx.x;
    if (p0 >= NPIX) return;
    const int h = p0 / Ww, w0 = p0 % Ww;   /* w0 multiple of 4, no row cross */
    const bool leftok  = (w0 > 0);
    const bool rightok = (w0 + 4 < Ww);

    ull m12[4][4];     /* [px][out] packed (m1,m2) */
    ull m3 [4][2];     /* [px][outpair]            */
    #pragma unroll
    for (int px = 0; px < 4; px++){
        #pragma unroll
        for (int o = 0; o < 4; o++) m12[px][o] = 0ULL;
        m3[px][0] = 0ULL; m3[px][1] = 0ULL;
    }

    const float2* ip = in + (size_t)b*CS*NPIX;
    for (int c = 0; c < CS; c++, ip += NPIX){
        float2 q[3][6];
        #pragma unroll
        for (int ky = 0; ky < 3; ky++){
            int gy = h + ky - 1;
            bool rv = (gy >= 0) && (gy < Hh);
            const float2* rp = ip + gy*Ww + w0;
            if (rv){
                float4 a0 = *(const float4*)rp;        /* px 0,1 */
                float4 a1 = *(const float4*)(rp + 2);  /* px 2,3 */
                q[ky][1] = make_float2(a0.x, a0.y);
                q[ky][2] = make_float2(a0.z, a0.w);
                q[ky][3] = make_float2(a1.x, a1.y);
                q[ky][4] = make_float2(a1.z, a1.w);
                q[ky][0] = leftok  ? rp[-1] : make_float2(0.f, 0.f);
                q[ky][5] = rightok ? rp[4]  : make_float2(0.f, 0.f);
            } else {
                #pragma unroll
                for (int i = 0; i < 6; i++) q[ky][i] = make_float2(0.f, 0.f);
            }
        }
        #pragma unroll
        for (int ky = 0; ky < 3; ky++){
            ull xri[6], xs[6];
            #pragma unroll
            for (int i = 0; i < 6; i++){
                xri[i] = pk2(q[ky][i].x, q[ky][i].y);
                float s = q[ky][i].x + q[ky][i].y;
                xs[i]  = pk2(s, s);
            }
            #pragma unroll
            for (int kx = 0; kx < 3; kx++){
                const int tap = ky*3 + kx;
                const ulonglong2* wp  = (const ulonglong2*)(swp + (c*9 + tap)*4);
                const ulonglong2* wsp = ((const ulonglong2*)sws) + (c*9 + tap);
                ulonglong2 wv0 = wp[0], wv1 = wp[1];
                ulonglong2 sv  = wsp[0];
                #pragma unroll
                for (int px = 0; px < 4; px++){
                    ull xe = xri[kx+px];
                    ull se = xs[kx+px];
                    fma2(m12[px][0], xe, wv0.x);
                    fma2(m12[px][1], xe, wv0.y);
                    fma2(m12[px][2], xe, wv1.x);
                    fma2(m12[px][3], xe, wv1.y);
                    fma2(m3[px][0], se, sv.x);
                    fma2(m3[px][1], se, sv.y);
                }
            }
        }
    }

    #pragma unroll
    for (int o = 0; o < 4; o++){
        const size_t ch = (size_t)b*32 + z*4 + o;
        float2* op = out + ch*NPIX + p0;
        const float2* ap = act + ch*NPIX + p0;
        #pragma unroll
        for (int pq = 0; pq < 2; pq++){          /* pixel pairs: (0,1),(2,3) */
            float4 av;
            if (EPI == 2) av = *(const float4*)(ap + 2*pq);
            float4 ov;
            #pragma unroll
            for (int k = 0; k < 2; k++){
                int px = 2*pq + k;
                float m1, m2; upk2(m12[px][o], m1, m2);
                float g3a, g3b; upk2(m3[px][o>>1], g3a, g3b);
                float m3v = (o & 1) ? g3b : g3a;
                float re = m1 - m2;
                float im = m3v - m1 - m2;
                if (EPI == 1){ re = actf(re); im = actf(im); }
                if (EPI == 2){
                    float ar = (k == 0) ? av.x : av.z;
                    float ai = (k == 0) ? av.y : av.w;
                    float dr = actd(ar), di = actd(ai);
                    float nre = re*dr - im*di;
                    im = re*di + im*dr;
                    re = nre;
                }
                if (k == 0){ ov.x = re; ov.y = im; } else { ov.z = re; ov.w = im; }
            }
            *(float4*)(op + 2*pq) = ov;
        }
    }
}

/* ------------- fused 32->1 transposed conv + gradient update ---------------- */
__global__ void __launch_bounds__(256)
k_t1_update(const float2* __restrict__ in,
            const float* __restrict__ w1rA, const float* __restrict__ w1iA,
            const float* __restrict__ w1rB, const float* __restrict__ w1iB,
            const float2* __restrict__ gf, const float2* __restrict__ cc,
            float2* __restrict__ X,
            const float* __restrict__ al1, const float* __restrict__ al2,
            const float* __restrict__ be1, const float* __restrict__ be2, int ph)
{
    __shared__ ulonglong2 sxt[4][10][34];
    __shared__ ulonglong2 swt[32][9];
    const int tx = threadIdx.x & 31, ty = threadIdx.x >> 5;
    const int tid = threadIdx.x;
    const int wx0 = blockIdx.x*32, hy0 = blockIdx.y*8;
    const int b = blockIdx.z;
    const float* wr = (b < Bb) ? w1rA : w1rB;
    const float* wi = (b < Bb) ? w1iA : w1iB;

    for (int t = tid; t < 288; t += 256){
        int c = t / 9, tap = t % 9;
        int ky = tap/3, kx = tap%3;
        int ft = (2-ky)*3 + (2-kx);
        float a = wr[c*9 + ft], bq = wi[c*9 + ft];
        swt[c][tap] = make_ulonglong2(pk2(a, bq), pk2(bq, a));
    }

    const float2* ib = in + (size_t)b*32*NPIX;
    ull acc = 0ULL;
    for (int cs = 0; cs < 8; cs++){
        __syncthreads();
        for (int t = tid; t < 4*340; t += 256){
            int ch = t / 340, e = t % 340;
            int yy = e / 34, xx = e % 34;
            int gy = hy0 + yy - 1, gx = wx0 + xx - 1;
            float2 v = make_float2(0.f, 0.f);
            if (gy >= 0 && gy < Hh && gx >= 0 && gx < Ww)
                v = ib[(size_t)(cs*4+ch)*NPIX + gy*Ww + gx];
            sxt[ch][yy][xx] = make_ulonglong2(pk2(v.x, v.x), pk2(-v.y, v.y));
        }
        __syncthreads();
        #pragma unroll
        for (int ch = 0; ch < 4; ch++){
            int c = cs*4 + ch;
            #pragma unroll
            for (int tap = 0; tap < 9; tap++){
                int ky = tap/3, kx = tap%3;
                ulonglong2 wv = swt[c][tap];
                ulonglong2 xv = sxt[ch][ty+ky][tx+kx];
                fma2(acc, xv.x, wv.x);
                fma2(acc, xv.y, wv.y);
            }
        }
    }
    int h = hy0 + ty, w = wx0 + tx;
    if (w < Ww){
        float gr, gi; upk2(acc, gr, gi);
        size_t i = (size_t)b*NPIX + h*Ww + w;
        float a  = (b < Bb) ? al1[ph] : al2[ph];
        float be = (b < Bb) ? be1[ph] : be2[ph];
        float2 xv = X[i], f = gf[i], c = cc[i];
        xv.x -= a*(f.x - c.x) + be*gr;
        xv.y -= a*(f.y - c.y) + be*gi;
        X[i] = xv;
    }
}

/* ------------------------- threshold / normalize --------------------------- */
__global__ void k_thresh(const float2* __restrict__ in, float2* __restrict__ out,
                         const float* __restrict__ thr1, const float* __restrict__ thr2){
    int p = blockIdx.x*blockDim.x + threadIdx.x;
    int b = blockIdx.y;
    if (p >= NPIX) return;
    float thr = (b < Bb) ? thr1[0] : thr2[0];
    const float2* ip = in + (size_t)b*32*NPIX + p;
    float nrm = 0.f;
    #pragma unroll 8
    for (int c = 0; c < 32; c++){
        float2 v = ip[(size_t)c*NPIX];
        nrm = fmaf(v.x, v.x, nrm);
        nrm = fmaf(v.y, v.y, nrm);
    }
    nrm = sqrtf(nrm);
    float denom = (nrm > thr) ? fmaxf(nrm, 1e-12f) : thr;
    float inv = 1.f/denom;
    float2* op = out + (size_t)b*32*NPIX + p;
    #pragma unroll 8
    for (int c = 0; c < 32; c++){
        float2 v = ip[(size_t)c*NPIX];
        op[(size_t)c*NPIX] = make_float2(v.x*inv, v.y*inv);
    }
}

__global__ void k_out(const float2* __restrict__ X, float* __restrict__ o){
    int i = blockIdx.x*blockDim.x + threadIdx.x;
    if (i >= NIMG) return;
    int b = i / NPIX, p = i % NPIX;
    size_t base = (size_t)b*4*NPIX + p;
    float2 v1 = X[(size_t)b*NPIX + p];
    float2 v2 = X[(size_t)(b+Bb)*NPIX + p];
    o[base + 0*NPIX] = v1.x;
    o[base + 1*NPIX] = v1.y;
    o[base + 2*NPIX] = v2.x;
    o[base + 3*NPIX] = v2.y;
}

/* --------------------------------- launch ---------------------------------- */
static inline void* symaddr(const void* sym){
    void* p = nullptr;
    cudaGetSymbolAddress(&p, sym);
    return p;
}

extern "C" void kernel_launch(void* const* d_in, const int* in_sizes, int n_in,
                              void* d_out, int out_size){
    const float* x1in  = (const float*)d_in[0];
    const float* x2in  = (const float*)d_in[1];
    const float* k1in  = (const float*)d_in[2];
    const float* k2in  = (const float*)d_in[3];
    const float* mask  = (const float*)d_in[4];
    const float* wA[8], *wB[8];
    for (int j = 0; j < 8; j++){ wA[j] = (const float*)d_in[5+j]; wB[j] = (const float*)d_in[13+j]; }
    const float* thr1  = (const float*)d_in[21];
    const float* thr2  = (const float*)d_in[22];
    const float* al1   = (const float*)d_in[23];
    const float* al2   = (const float*)d_in[24];
    const float* be1   = (const float*)d_in[25];
    const float* be2   = (const float*)d_in[26];

    float2* X   = (float2*)symaddr(g_X);
    float2* C   = (float2*)symaddr(g_C);
    float2* TA  = (float2*)symaddr(g_ta);
    float2* TB  = (float2*)symaddr(g_tb);
    float2* GF  = (float2*)symaddr(g_gf);
    float2* A0  = (float2*)symaddr(g_act0);
    float2* A1  = (float2*)symaddr(g_act1);
    float2* A2  = (float2*)symaddr(g_act2);
    float2* F0  = (float2*)symaddr(g_fb0);
    float2* F1  = (float2*)symaddr(g_fb1);
    ulonglong2* TW   = (ulonglong2*)symaddr(g_twW);
    ulonglong2* TWi  = (ulonglong2*)symaddr(g_twWi);
    ulonglong2* MH2  = (ulonglong2*)symaddr(g_MH2);
    ulonglong2* MH2i = (ulonglong2*)symaddr(g_MH2i);

    const int TPB = 256;
    const int gIMG1 = (NIMG  + TPB - 1)/TPB;
    const int gIMG2 = (NIMG2 + TPB - 1)/TPB;
    const int gPIX  = (NPIX  + TPB - 1)/TPB;
    const int gPX4  = (NPIX  + 511)/512;           /* 57 */
    dim3 gridConv(gPX4*8, B2);         /* bx = colb*8 + z (z adjacent) */
    dim3 gridThr (gPIX, B2);
    dim3 gridRow ((B2*Hh)/8);
    dim3 gridCol (Hh/8, B2);
    dim3 gridT1  ((Ww+31)/32, Hh/8, B2);
    const int SMEM_H = 32*9*4*8 + 32*9*4*4;        /* 13824 B */
    const int SMEM_1 = 1*9*4*8 + 1*9*4*4;

    k_init_dft<<<(Hh*Hh + TPB - 1)/TPB, TPB>>>();
    k_pack2<<<gIMG2, TPB>>>(x1in, x2in, X);

    for (int ph = 0; ph < 3; ph++){
        /* grad_r chain first (keeps the heavy conv at ncu's launch #6) */
        k_conv4<1, 0, 1><<<gridConv, 128, SMEM_1>>>(X,  wA[0], wA[1], wB[0], wB[1], A0, nullptr);
        k_conv4<32,0, 1><<<gridConv, 128, SMEM_H>>>(A0, wA[2], wA[3], wB[2], wB[3], A1, nullptr);
        k_conv4<32,0, 1><<<gridConv, 128, SMEM_H>>>(A1, wA[4], wA[5], wB[4], wB[5], A2, nullptr);
        k_conv4<32,0, 0><<<gridConv, 128, SMEM_H>>>(A2, wA[6], wA[7], wB[6], wB[7], F0, nullptr);
        k_thresh<<<gridThr, TPB>>>(F0, F1, thr1, thr2);
        k_conv4<32,1, 2><<<gridConv, 128, SMEM_H>>>(F1, wA[6], wA[7], wB[6], wB[7], F0, A2);
        k_conv4<32,1, 2><<<gridConv, 128, SMEM_H>>>(F0, wA[4], wA[5], wB[4], wB[5], F1, A1);
        k_conv4<32,1, 2><<<gridConv, 128, SMEM_H>>>(F1, wA[2], wA[3], wB[2], wB[3], F0, A0);

        if (ph == 0){
            k_maskk2<<<gIMG2, TPB>>>(k1in, k2in, mask, TA);
            k_dftrow<<<gridRow, 360>>>(TA, TB, TWi);
            k_dftcol<0><<<gridCol, 360>>>(TB, C, MH2i, nullptr);
        }

        /* grad_f (minus constant): GF = IFFT2(mask^2 * FFT2(X)) */
        k_dftrow<<<gridRow, 360>>>(X,  TA, TW);
        k_dftcol<1><<<gridCol, 360>>>(TA, TB, MH2, mask);
        k_dftrow<<<gridRow, 360>>>(TB, TA, TWi);
        k_dftcol<0><<<gridCol, 360>>>(TA, GF, MH2i, nullptr);

        /* 32->1 transposed conv fused with the x update */
        k_t1_update<<<gridT1, 256>>>(F0, wA[0], wA[1], wB[0], wB[1],
                                     GF, C, X, al1, al2, be1, be2, ph);
    }
    k_out<<<gIMG1, TPB>>>(X, (float*)d_out);
}